// round 1
// baseline (speedup 1.0000x reference)
#include <cuda_runtime.h>

#define B_  16
#define N_  1024
#define H_  224
#define W_  224
#define KS  23
#define HALF 11
#define SIGMA2X2 18.0f   // 2 * 3.0^2

// Scratch: intermediate separable accumulation A[B,H,W] and the 1-D kernel.
__device__ float g_A[B_ * H_ * W_];
__device__ float g_k1[KS];

// Kernel 1: zero A; first warp also computes the normalized 1-D Gaussian.
__global__ void init_kernel() {
    int tid = blockIdx.x * blockDim.x + threadIdx.x;
    // grid-stride zero of A
    for (int i = tid; i < B_ * H_ * W_; i += gridDim.x * blockDim.x)
        g_A[i] = 0.0f;

    if (blockIdx.x == 0 && threadIdx.x < 32) {
        int lane = threadIdx.x;
        float d = (float)lane - (float)(KS - 1) * 0.5f;  // lane - 11
        float v = (lane < KS) ? expf(-(d * d) / SIGMA2X2) : 0.0f;
        // warp reduce sum
        float s = v;
        #pragma unroll
        for (int off = 16; off > 0; off >>= 1)
            s += __shfl_xor_sync(0xFFFFFFFFu, s, off);
        if (lane < KS)
            g_k1[lane] = v / s;
    }
}

// Kernel 2: scatter 1-D x-profiles. One thread per (b, n) point.
__global__ void scatter_kernel(const float* __restrict__ points) {
    int i = blockIdx.x * blockDim.x + threadIdx.x;
    if (i >= B_ * N_) return;

    float2 p = reinterpret_cast<const float2*>(points)[i];
    int x = (int)(p.x * (float)W_);   // truncation == astype(int32) for nonneg
    int y = (int)(p.y * (float)H_);
    int b = i >> 10;                  // N_ = 1024

    if ((unsigned)y >= (unsigned)H_) return;  // pathological fp rounding guard

    float* row = g_A + (b * H_ + y) * W_;
    #pragma unroll
    for (int j = 0; j < KS; j++) {
        int c = x + j - HALF;
        if ((unsigned)c < (unsigned)W_)
            atomicAdd(row + c, g_k1[j]);
    }
}

// Kernel 3: 23-tap 1-D convolution along y, float4 vectorized over x.
// out[b,r,c] = sum_j k1[j] * A[b, r+j-11, c]
__global__ void conv_kernel(float* __restrict__ out) {
    const int W4 = W_ / 4;  // 56
    int idx = blockIdx.x * blockDim.x + threadIdx.x;
    if (idx >= B_ * H_ * W4) return;

    int c4 = idx % W4;
    int t  = idx / W4;
    int r  = t % H_;
    int b  = t / H_;

    float4 acc = make_float4(0.f, 0.f, 0.f, 0.f);
    #pragma unroll
    for (int j = 0; j < KS; j++) {
        int rr = r + j - HALF;
        if ((unsigned)rr < (unsigned)H_) {
            const float4 v = *reinterpret_cast<const float4*>(
                g_A + ((b * H_ + rr) * W_) + c4 * 4);
            float w = g_k1[j];
            acc.x = fmaf(w, v.x, acc.x);
            acc.y = fmaf(w, v.y, acc.y);
            acc.z = fmaf(w, v.z, acc.z);
            acc.w = fmaf(w, v.w, acc.w);
        }
    }
    reinterpret_cast<float4*>(out)[idx] = acc;
}

extern "C" void kernel_launch(void* const* d_in, const int* in_sizes, int n_in,
                              void* d_out, int out_size) {
    // d_in[0] = feature_map (unused beyond shape), d_in[1] = points [B,N,2] f32
    const float* points = (const float*)d_in[1];
    float* out = (float*)d_out;

    init_kernel<<<3136, 256>>>();
    scatter_kernel<<<(B_ * N_ + 255) / 256, 256>>>(points);
    conv_kernel<<<(B_ * H_ * (W_ / 4) + 255) / 256, 256>>>(out);
}